// round 14
// baseline (speedup 1.0000x reference)
#include <cuda_runtime.h>
#include <cuda_fp16.h>
#include <math.h>
#include <stdint.h>

#define NMAX 100000
#define EMAX 2000000

// Scratch (alloc-free: __device__ globals, zero-initialized at load)
__device__ __half g_t16a[NMAX * 64];   // layer-1 linear output (fp16)
__device__ __half g_t16b[NMAX * 64];   // layer-2 linear output (fp16)
__device__ float  g_t32[NMAX * 64];    // reused: layer-3 linear output as fp16
__device__ float  g_h[NMAX * 64];      // reused as TWO half buffers (act1, act2)
__device__ int    g_deg[NMAX];         // self-cleaning (scan3 re-zeroes)
__device__ int    g_incl[NMAX];
__device__ int    g_rp[NMAX + 1];
__device__ int    g_cursor[NMAX];
__device__ int    g_bsum[128];
__device__ int    g_csr[EMAX];
// W1 tf32 fragments (8192 u32) + W2 fp16 (2048) + W3 fp16 (2048)
__device__ __align__(16) uint32_t g_wf[8192 + 2048 + 2048];

__device__ __forceinline__ uint32_t f2tf32(float f) {
    uint32_t r;
    asm("cvt.rna.tf32.f32 %0, %1;" : "=r"(r) : "f"(f));
    return r;
}

__device__ __forceinline__ void cp_async16(uint32_t saddr, const void* gptr, bool valid) {
    int sz = valid ? 16 : 0;
    asm volatile("cp.async.cg.shared.global [%0], [%1], 16, %2;"
                 :: "r"(saddr), "l"(gptr), "r"(sz));
}

// ---------------------------------------------------------------------------
// hist + W prep merged. Block 0: W1 tf32 paired-uint4 layout.
// Blocks 1,2: W2/W3 fp16 m16n8k16 fragment layout. Rest: degree histogram.
// ---------------------------------------------------------------------------
__global__ __launch_bounds__(256)
void hist_wprep_kernel(const int* __restrict__ ei, int E, int* __restrict__ deg,
                       const float* __restrict__ W1, const float* __restrict__ W2,
                       const float* __restrict__ W3, uint32_t* __restrict__ wf) {
    if (blockIdx.x == 0) {
        for (int idx = threadIdx.x; idx < 128 * 64; idx += 256) {
            int k  = idx >> 6;
            int nn = idx & 63;
            int ks = k >> 3, kk = k & 7;
            int ch = kk >> 2, c = kk & 3;
            int nb = nn >> 3, ng = nn & 7;
            int lane = ng * 4 + c;
            int pos = (((ks * 4 + (nb >> 1)) * 32) + lane) * 4 + (nb & 1) * 2 + ch;
            wf[pos] = f2tf32(W1[idx]);
        }
    } else if (blockIdx.x <= 2) {
        const float* W = (blockIdx.x == 1) ? W2 : W3;
        uint32_t* dst = wf + 8192 + (blockIdx.x - 1) * 2048;
        for (int u = threadIdx.x; u < 2048; u += 256) {
            int reg  = u & 1;
            int lane = (u >> 1) & 31;
            int nb   = (u >> 6) & 7;
            int ks16 = u >> 9;
            int tig = lane & 3, grp = lane >> 2;
            int k0 = ks16 * 16 + reg * 8 + tig * 2;
            int n  = nb * 8 + grp;
            __half2 hv = __floats2half2_rn(W[k0 * 64 + n], W[(k0 + 1) * 64 + n]);
            int pos = (((ks16 * 4 + (nb >> 1)) * 32) + lane) * 4 + (nb & 1) * 2 + reg;
            dst[pos] = *(uint32_t*)&hv;
        }
    } else {
        int e = (blockIdx.x - 3) * 256 + threadIdx.x;
        if (e < E) atomicAdd(&deg[ei[E + e]], 1);
    }
}

// ---------------------------------------------------------------------------
// Layer-1 GEMM: tf32, fp32 input. 64 rows/block, 3-stage cp.async pipeline.
// ---------------------------------------------------------------------------
__global__ __launch_bounds__(256)
void gemm_tf32_kernel(const float* __restrict__ in, const uint32_t* __restrict__ wf,
                      __half* __restrict__ out, int n) {
    constexpr int NCHUNK = 4;   // K = 128
    __shared__ float hT[3][64][36];

    const int tid  = threadIdx.x;
    const int w    = tid >> 5;
    const int lane = tid & 31;
    const int grp  = lane >> 2;
    const int tig  = lane & 3;
    const int wg   = w >> 1;
    const int cw   = w & 1;
    const int row0 = blockIdx.x * 64;

    const int lr0 = wg * 16 + grp;
    const int lr1 = lr0 + 8;
    const uint4* wf4 = (const uint4*)wf;

    float acc[4][4];
#pragma unroll
    for (int nb = 0; nb < 4; nb++)
#pragma unroll
        for (int j = 0; j < 4; j++) acc[nb][j] = 0.f;

    auto stage = [&](int c, int buf) {
#pragma unroll
        for (int it = 0; it < 2; it++) {
            int idx = tid + it * 256;
            int r = idx >> 3;
            int q = idx & 7;
            int grow = row0 + r;
            uint32_t sa = (uint32_t)__cvta_generic_to_shared(&hT[buf][r][q * 4]);
            cp_async16(sa, &in[(long)grow * 128 + c * 32 + q * 4], grow < n);
        }
        asm volatile("cp.async.commit_group;");
    };

    stage(0, 0);
    stage(1, 1);

#pragma unroll
    for (int c = 0; c < NCHUNK; c++) {
        if (c == NCHUNK - 1) asm volatile("cp.async.wait_group 0;");
        else                 asm volatile("cp.async.wait_group 1;");
        __syncthreads();
        if (c + 2 < NCHUNK) stage(c + 2, (c + 2) % 3);

        const int buf = c % 3;
#pragma unroll
        for (int ks = 0; ks < 4; ks++) {
            uint32_t a0 = f2tf32(hT[buf][lr0][ks * 8 + tig]);
            uint32_t a1 = f2tf32(hT[buf][lr1][ks * 8 + tig]);
            uint32_t a2 = f2tf32(hT[buf][lr0][ks * 8 + tig + 4]);
            uint32_t a3 = f2tf32(hT[buf][lr1][ks * 8 + tig + 4]);

            const uint4* wbase = wf4 + ((c * 4 + ks) * 4 + cw * 2) * 32 + lane;
#pragma unroll
            for (int nbp = 0; nbp < 2; nbp++) {
                uint4 bb = __ldg(wbase + nbp * 32);
                asm volatile(
                    "mma.sync.aligned.m16n8k8.row.col.f32.tf32.tf32.f32 "
                    "{%0,%1,%2,%3}, {%4,%5,%6,%7}, {%8,%9}, {%0,%1,%2,%3};"
                    : "+f"(acc[nbp*2][0]), "+f"(acc[nbp*2][1]),
                      "+f"(acc[nbp*2][2]), "+f"(acc[nbp*2][3])
                    : "r"(a0), "r"(a1), "r"(a2), "r"(a3),
                      "r"(bb.x), "r"(bb.y));
                asm volatile(
                    "mma.sync.aligned.m16n8k8.row.col.f32.tf32.tf32.f32 "
                    "{%0,%1,%2,%3}, {%4,%5,%6,%7}, {%8,%9}, {%0,%1,%2,%3};"
                    : "+f"(acc[nbp*2+1][0]), "+f"(acc[nbp*2+1][1]),
                      "+f"(acc[nbp*2+1][2]), "+f"(acc[nbp*2+1][3])
                    : "r"(a0), "r"(a1), "r"(a2), "r"(a3),
                      "r"(bb.z), "r"(bb.w));
            }
        }
    }

    const int r0 = row0 + lr0;
    const int r1 = row0 + lr1;
    const bool v0 = r0 < n;
    const bool v1 = r1 < n;
#pragma unroll
    for (int nb = 0; nb < 4; nb++) {
        int col = cw * 32 + nb * 8 + tig * 2;
        if (v0) *(__half2*)&out[(long)r0 * 64 + col] = __floats2half2_rn(acc[nb][0], acc[nb][1]);
        if (v1) *(__half2*)&out[(long)r1 * 64 + col] = __floats2half2_rn(acc[nb][2], acc[nb][3]);
    }
}

// ---------------------------------------------------------------------------
// Layers 2-3 GEMM: fp16 m16n8k16, half input/output (K=64, single stage).
// ---------------------------------------------------------------------------
__global__ __launch_bounds__(256)
void gemm_fp16_kernel(const __half* __restrict__ in, const uint32_t* __restrict__ wf,
                      __half* __restrict__ out, int n) {
    __shared__ __half hs[64][72];   // stride 72 halves (144B): conflict-free frags

    const int tid  = threadIdx.x;
    const int w    = tid >> 5;
    const int lane = tid & 31;
    const int grp  = lane >> 2;
    const int tig  = lane & 3;
    const int wg   = w >> 1;
    const int cw   = w & 1;
    const int row0 = blockIdx.x * 64;

    const int lr0 = wg * 16 + grp;
    const int lr1 = lr0 + 8;
    const uint4* wf4 = (const uint4*)wf;

#pragma unroll
    for (int it = 0; it < 2; it++) {
        int idx = tid + it * 256;
        int r = idx >> 3;
        int q = idx & 7;
        int grow = row0 + r;
        uint32_t sa = (uint32_t)__cvta_generic_to_shared(&hs[r][q * 8]);
        cp_async16(sa, &in[(long)grow * 64 + q * 8], grow < n);
    }
    asm volatile("cp.async.commit_group;");

    float acc[4][4];
#pragma unroll
    for (int nb = 0; nb < 4; nb++)
#pragma unroll
        for (int j = 0; j < 4; j++) acc[nb][j] = 0.f;

    asm volatile("cp.async.wait_group 0;");
    __syncthreads();

#pragma unroll
    for (int ks = 0; ks < 4; ks++) {
        uint32_t a0 = *(const uint32_t*)&hs[lr0][ks * 16 + tig * 2];
        uint32_t a1 = *(const uint32_t*)&hs[lr1][ks * 16 + tig * 2];
        uint32_t a2 = *(const uint32_t*)&hs[lr0][ks * 16 + 8 + tig * 2];
        uint32_t a3 = *(const uint32_t*)&hs[lr1][ks * 16 + 8 + tig * 2];

        const uint4* wbase = wf4 + (ks * 4 + cw * 2) * 32 + lane;
#pragma unroll
        for (int nbp = 0; nbp < 2; nbp++) {
            uint4 bb = __ldg(wbase + nbp * 32);
            asm volatile(
                "mma.sync.aligned.m16n8k16.row.col.f32.f16.f16.f32 "
                "{%0,%1,%2,%3}, {%4,%5,%6,%7}, {%8,%9}, {%0,%1,%2,%3};"
                : "+f"(acc[nbp*2][0]), "+f"(acc[nbp*2][1]),
                  "+f"(acc[nbp*2][2]), "+f"(acc[nbp*2][3])
                : "r"(a0), "r"(a1), "r"(a2), "r"(a3),
                  "r"(bb.x), "r"(bb.y));
            asm volatile(
                "mma.sync.aligned.m16n8k16.row.col.f32.f16.f16.f32 "
                "{%0,%1,%2,%3}, {%4,%5,%6,%7}, {%8,%9}, {%0,%1,%2,%3};"
                : "+f"(acc[nbp*2+1][0]), "+f"(acc[nbp*2+1][1]),
                  "+f"(acc[nbp*2+1][2]), "+f"(acc[nbp*2+1][3])
                : "r"(a0), "r"(a1), "r"(a2), "r"(a3),
                  "r"(bb.z), "r"(bb.w));
        }
    }

    const int r0 = row0 + lr0;
    const int r1 = row0 + lr1;
    const bool v0 = r0 < n;
    const bool v1 = r1 < n;
#pragma unroll
    for (int nb = 0; nb < 4; nb++) {
        int col = cw * 32 + nb * 8 + tig * 2;
        if (v0) *(__half2*)&out[(long)r0 * 64 + col] = __floats2half2_rn(acc[nb][0], acc[nb][1]);
        if (v1) *(__half2*)&out[(long)r1 * 64 + col] = __floats2half2_rn(acc[nb][2], acc[nb][3]);
    }
}

// ---------------------------------------------------------------------------
// CSR construction (scan1, scan3, fill)
// ---------------------------------------------------------------------------
__global__ __launch_bounds__(256)
void scan1_kernel(const int* __restrict__ deg, int n,
                  int* __restrict__ incl, int* __restrict__ bsum) {
    __shared__ int s[1024];
    const int base = blockIdx.x * 1024;
    const int t = threadIdx.x;
#pragma unroll
    for (int j = 0; j < 4; j++) {
        int idx = t + j * 256;
        s[idx] = (base + idx < n) ? deg[base + idx] : 0;
    }
    __syncthreads();
    for (int off = 1; off < 1024; off <<= 1) {
        int v[4];
#pragma unroll
        for (int j = 0; j < 4; j++) {
            int idx = t + j * 256;
            v[j] = (idx >= off) ? s[idx - off] : 0;
        }
        __syncthreads();
#pragma unroll
        for (int j = 0; j < 4; j++) s[t + j * 256] += v[j];
        __syncthreads();
    }
#pragma unroll
    for (int j = 0; j < 4; j++) {
        int idx = t + j * 256;
        if (base + idx < n) incl[base + idx] = s[idx];
    }
    if (t == 0) bsum[blockIdx.x] = s[1023];
}

__global__ __launch_bounds__(256)
void scan3_kernel(const int* __restrict__ incl, int* __restrict__ deg,
                  const int* __restrict__ bsum, int nb, int n, int E,
                  int* __restrict__ rp, int* __restrict__ cursor) {
    __shared__ int s[128];
    const int t = threadIdx.x;
    if (t < 128) s[t] = (t < nb) ? bsum[t] : 0;
    __syncthreads();
    for (int off = 1; off < 128; off <<= 1) {
        int v = 0;
        if (t < 128 && t >= off) v = s[t - off];
        __syncthreads();
        if (t < 128) s[t] += v;
        __syncthreads();
    }
    int i = blockIdx.x * blockDim.x + t;
    if (i >= n) return;
    int b = i >> 10;
    int add = b ? s[b - 1] : 0;
    int excl = incl[i] - deg[i] + add;
    rp[i] = excl;
    cursor[i] = excl;
    deg[i] = 0;
    if (i == n - 1) rp[n] = E;
}

__global__ void fill_kernel(const int* __restrict__ ei, int E,
                            int* __restrict__ cursor, int* __restrict__ csr) {
    int e = blockIdx.x * blockDim.x + threadIdx.x;
    if (e >= E) return;
    int src = ei[e];
    int dst = ei[E + e];
    int pos = atomicAdd(&cursor[dst], 1);
    csr[pos] = src;
}

// ---------------------------------------------------------------------------
// Gather-reduce (fp16 t) + bias + relu -> fp16 h (for fp16 GEMM input)
// ---------------------------------------------------------------------------
__global__ __launch_bounds__(256)
void gather_h2_kernel(const int* __restrict__ rp, const int* __restrict__ csr,
                      const __half* __restrict__ t, const float* __restrict__ bias,
                      __half* __restrict__ out, int n) {
    int warp = (blockIdx.x * blockDim.x + threadIdx.x) >> 5;
    int lane = threadIdx.x & 31;
    if (warp >= n) return;

    int s0 = rp[warp];
    int s1 = rp[warp + 1];
    const __half2* tp = (const __half2*)t;

    float ax = 0.f, ay = 0.f, bx = 0.f, by = 0.f;
    int e = s0;
    for (; e + 15 < s1; e += 16) {
        int idx[16];
#pragma unroll
        for (int j = 0; j < 16; j++) idx[j] = __ldg(&csr[e + j]);
        float2 v[16];
#pragma unroll
        for (int j = 0; j < 16; j++)
            v[j] = __half22float2(tp[(long)idx[j] * 32 + lane]);
#pragma unroll
        for (int j = 0; j < 16; j += 4) {
            ax += v[j + 0].x + v[j + 2].x;  ay += v[j + 0].y + v[j + 2].y;
            bx += v[j + 1].x + v[j + 3].x;  by += v[j + 1].y + v[j + 3].y;
        }
    }
    for (; e + 3 < s1; e += 4) {
        int i0 = __ldg(&csr[e + 0]);
        int i1 = __ldg(&csr[e + 1]);
        int i2 = __ldg(&csr[e + 2]);
        int i3 = __ldg(&csr[e + 3]);
        float2 v0 = __half22float2(tp[(long)i0 * 32 + lane]);
        float2 v1 = __half22float2(tp[(long)i1 * 32 + lane]);
        float2 v2 = __half22float2(tp[(long)i2 * 32 + lane]);
        float2 v3 = __half22float2(tp[(long)i3 * 32 + lane]);
        ax += v0.x + v2.x;  ay += v0.y + v2.y;
        bx += v1.x + v3.x;  by += v1.y + v3.y;
    }
    for (; e < s1; e++) {
        int i0 = __ldg(&csr[e]);
        float2 v = __half22float2(tp[(long)i0 * 32 + lane]);
        ax += v.x; ay += v.y;
    }
    ax += bx; ay += by;

    float2 bb = *(const float2*)&bias[lane * 2];
    float rx = fmaxf(ax + bb.x, 0.f);
    float ry = fmaxf(ay + bb.y, 0.f);
    ((__half2*)out)[(long)warp * 32 + lane] = __floats2half2_rn(rx, ry);
}

// ---------------------------------------------------------------------------
// Final gather (fp16 t) + bias + sigmoid -> fp32 out
// ---------------------------------------------------------------------------
__global__ __launch_bounds__(256)
void gather_sig_kernel(const int* __restrict__ rp, const int* __restrict__ csr,
                       const __half* __restrict__ t, const float* __restrict__ bias,
                       float* __restrict__ out, int n) {
    int warp = (blockIdx.x * blockDim.x + threadIdx.x) >> 5;
    int lane = threadIdx.x & 31;
    if (warp >= n) return;

    int s0 = rp[warp];
    int s1 = rp[warp + 1];
    const __half2* tp = (const __half2*)t;

    float ax = 0.f, ay = 0.f, bx = 0.f, by = 0.f;
    int e = s0;
    for (; e + 15 < s1; e += 16) {
        int idx[16];
#pragma unroll
        for (int j = 0; j < 16; j++) idx[j] = __ldg(&csr[e + j]);
        float2 v[16];
#pragma unroll
        for (int j = 0; j < 16; j++)
            v[j] = __half22float2(tp[(long)idx[j] * 32 + lane]);
#pragma unroll
        for (int j = 0; j < 16; j += 4) {
            ax += v[j + 0].x + v[j + 2].x;  ay += v[j + 0].y + v[j + 2].y;
            bx += v[j + 1].x + v[j + 3].x;  by += v[j + 1].y + v[j + 3].y;
        }
    }
    for (; e + 3 < s1; e += 4) {
        int i0 = __ldg(&csr[e + 0]);
        int i1 = __ldg(&csr[e + 1]);
        int i2 = __ldg(&csr[e + 2]);
        int i3 = __ldg(&csr[e + 3]);
        float2 v0 = __half22float2(tp[(long)i0 * 32 + lane]);
        float2 v1 = __half22float2(tp[(long)i1 * 32 + lane]);
        float2 v2 = __half22float2(tp[(long)i2 * 32 + lane]);
        float2 v3 = __half22float2(tp[(long)i3 * 32 + lane]);
        ax += v0.x + v2.x;  ay += v0.y + v2.y;
        bx += v1.x + v3.x;  by += v1.y + v3.y;
    }
    for (; e < s1; e++) {
        int i0 = __ldg(&csr[e]);
        float2 v = __half22float2(tp[(long)i0 * 32 + lane]);
        ax += v.x; ay += v.y;
    }
    ax += bx; ay += by;

    float2 bb = *(const float2*)&bias[lane * 2];
    ax += bb.x; ay += bb.y;
    float2 r;
    r.x = 1.f / (1.f + __expf(-ax));
    r.y = 1.f / (1.f + __expf(-ay));
    *(float2*)&out[(long)warp * 64 + lane * 2] = r;
}

extern "C" void kernel_launch(void* const* d_in, const int* in_sizes, int n_in,
                              void* d_out, int out_size) {
    const float* x  = (const float*)d_in[0];
    const int*   ei = (const int*)d_in[1];
    const float* W1 = (const float*)d_in[2];
    const float* b1 = (const float*)d_in[3];
    const float* W2 = (const float*)d_in[4];
    const float* b2 = (const float*)d_in[5];
    const float* W3 = (const float*)d_in[6];
    const float* b3 = (const float*)d_in[7];
    float* out = (float*)d_out;

    const int N = in_sizes[0] / 128;
    const int E = in_sizes[1] / 2;

    __half *t16a, *t16b;
    float *t32buf, *hbuf;
    int *deg, *incl, *rp, *cursor, *bsum, *csr;
    uint32_t* wf;
    cudaGetSymbolAddress((void**)&t16a,   g_t16a);
    cudaGetSymbolAddress((void**)&t16b,   g_t16b);
    cudaGetSymbolAddress((void**)&t32buf, g_t32);
    cudaGetSymbolAddress((void**)&hbuf,   g_h);
    cudaGetSymbolAddress((void**)&deg,    g_deg);
    cudaGetSymbolAddress((void**)&incl,   g_incl);
    cudaGetSymbolAddress((void**)&rp,     g_rp);
    cudaGetSymbolAddress((void**)&cursor, g_cursor);
    cudaGetSymbolAddress((void**)&bsum,   g_bsum);
    cudaGetSymbolAddress((void**)&csr,    g_csr);
    cudaGetSymbolAddress((void**)&wf,     g_wf);

    __half* h16a = (__half*)hbuf;
    __half* h16b = (__half*)hbuf + (long)NMAX * 64;
    __half* t16c = (__half*)t32buf;     // layer-3 linear output, fp16

    const int nb_scan = (N + 1023) / 1024;
    const int nblk = (N + 255) / 256;
    const int eblk = (E + 255) / 256;
    const int gb64 = (N + 63) / 64;
    const int wb   = (N + 7) / 8;

    hist_wprep_kernel<<<eblk + 3, 256>>>(ei, E, deg, W1, W2, W3, wf);        // 1
    scan1_kernel<<<nb_scan, 256>>>(deg, N, incl, bsum);                      // 2
    scan3_kernel<<<nblk, 256>>>(incl, deg, bsum, nb_scan, N, E, rp, cursor); // 3
    gemm_tf32_kernel<<<gb64, 256>>>(x, wf, t16a, N);                         // 4 (profiled)
    fill_kernel<<<eblk, 256>>>(ei, E, cursor, csr);                          // 5

    gather_h2_kernel<<<wb, 256>>>(rp, csr, t16a, b1, h16a, N);               // 6
    gemm_fp16_kernel<<<gb64, 256>>>(h16a, wf + 8192, t16b, N);               // 7
    gather_h2_kernel<<<wb, 256>>>(rp, csr, t16b, b2, h16b, N);               // 8
    gemm_fp16_kernel<<<gb64, 256>>>(h16b, wf + 10240, t16c, N);              // 9
    gather_sig_kernel<<<wb, 256>>>(rp, csr, t16c, b3, out, N);               // 10
}

// round 15
// speedup vs baseline: 1.0022x; 1.0022x over previous
#include <cuda_runtime.h>
#include <cuda_fp16.h>
#include <math.h>
#include <stdint.h>

#define NMAX 100000
#define EMAX 2000000

// Scratch (alloc-free: __device__ globals, zero-initialized at load)
__device__ __half g_t16a[NMAX * 64];   // layer-1 linear output (fp16)
__device__ __half g_t16b[NMAX * 64];   // layer-2 linear output (fp16)
__device__ float  g_t32[NMAX * 64];    // layer-3 linear output (fp32)
__device__ float  g_h[NMAX * 64];      // reused as TWO half buffers (act1, act2)
__device__ int    g_deg[NMAX];         // self-cleaning (scan3 re-zeroes)
__device__ int    g_incl[NMAX];
__device__ int    g_rp[NMAX + 1];
__device__ int    g_cursor[NMAX];
__device__ int    g_bsum[128];
__device__ int    g_csr[EMAX];
// W1 tf32 fragments (8192 u32) + W2 fp16 (2048) + W3 fp16 (2048)
__device__ __align__(16) uint32_t g_wf[8192 + 2048 + 2048];

__device__ __forceinline__ uint32_t f2tf32(float f) {
    uint32_t r;
    asm("cvt.rna.tf32.f32 %0, %1;" : "=r"(r) : "f"(f));
    return r;
}

__device__ __forceinline__ void cp_async16(uint32_t saddr, const void* gptr, bool valid) {
    int sz = valid ? 16 : 0;
    asm volatile("cp.async.cg.shared.global [%0], [%1], 16, %2;"
                 :: "r"(saddr), "l"(gptr), "r"(sz));
}

// ---------------------------------------------------------------------------
// hist + W prep merged. Block 0: W1 tf32. Blocks 1,2: W2/W3 fp16 fragments.
// Rest: degree histogram, 4 edges/thread via int4 loads.
// ---------------------------------------------------------------------------
__global__ __launch_bounds__(256)
void hist_wprep_kernel(const int* __restrict__ ei, int E, int* __restrict__ deg,
                       const float* __restrict__ W1, const float* __restrict__ W2,
                       const float* __restrict__ W3, uint32_t* __restrict__ wf) {
    if (blockIdx.x == 0) {
        for (int idx = threadIdx.x; idx < 128 * 64; idx += 256) {
            int k  = idx >> 6;
            int nn = idx & 63;
            int ks = k >> 3, kk = k & 7;
            int ch = kk >> 2, c = kk & 3;
            int nb = nn >> 3, ng = nn & 7;
            int lane = ng * 4 + c;
            int pos = (((ks * 4 + (nb >> 1)) * 32) + lane) * 4 + (nb & 1) * 2 + ch;
            wf[pos] = f2tf32(W1[idx]);
        }
    } else if (blockIdx.x <= 2) {
        const float* W = (blockIdx.x == 1) ? W2 : W3;
        uint32_t* dst = wf + 8192 + (blockIdx.x - 1) * 2048;
        for (int u = threadIdx.x; u < 2048; u += 256) {
            int reg  = u & 1;
            int lane = (u >> 1) & 31;
            int nb   = (u >> 6) & 7;
            int ks16 = u >> 9;
            int tig = lane & 3, grp = lane >> 2;
            int k0 = ks16 * 16 + reg * 8 + tig * 2;
            int n  = nb * 8 + grp;
            __half2 hv = __floats2half2_rn(W[k0 * 64 + n], W[(k0 + 1) * 64 + n]);
            int pos = (((ks16 * 4 + (nb >> 1)) * 32) + lane) * 4 + (nb & 1) * 2 + reg;
            dst[pos] = *(uint32_t*)&hv;
        }
    } else {
        int e0 = ((blockIdx.x - 3) * 256 + threadIdx.x) * 4;
        if (e0 + 3 < E && (E & 3) == 0) {
            int4 d4 = *(const int4*)&ei[E + e0];
            atomicAdd(&deg[d4.x], 1);
            atomicAdd(&deg[d4.y], 1);
            atomicAdd(&deg[d4.z], 1);
            atomicAdd(&deg[d4.w], 1);
        } else {
            for (int j = 0; j < 4; j++) {
                int e = e0 + j;
                if (e < E) atomicAdd(&deg[ei[E + e]], 1);
            }
        }
    }
}

// ---------------------------------------------------------------------------
// Layer-1 GEMM: tf32, fp32 input. 64 rows/block, 3-stage cp.async pipeline.
// ---------------------------------------------------------------------------
__global__ __launch_bounds__(256)
void gemm_tf32_kernel(const float* __restrict__ in, const uint32_t* __restrict__ wf,
                      __half* __restrict__ out, int n) {
    constexpr int NCHUNK = 4;   // K = 128
    __shared__ float hT[3][64][36];

    const int tid  = threadIdx.x;
    const int w    = tid >> 5;
    const int lane = tid & 31;
    const int grp  = lane >> 2;
    const int tig  = lane & 3;
    const int wg   = w >> 1;
    const int cw   = w & 1;
    const int row0 = blockIdx.x * 64;

    const int lr0 = wg * 16 + grp;
    const int lr1 = lr0 + 8;
    const uint4* wf4 = (const uint4*)wf;

    float acc[4][4];
#pragma unroll
    for (int nb = 0; nb < 4; nb++)
#pragma unroll
        for (int j = 0; j < 4; j++) acc[nb][j] = 0.f;

    auto stage = [&](int c, int buf) {
#pragma unroll
        for (int it = 0; it < 2; it++) {
            int idx = tid + it * 256;
            int r = idx >> 3;
            int q = idx & 7;
            int grow = row0 + r;
            uint32_t sa = (uint32_t)__cvta_generic_to_shared(&hT[buf][r][q * 4]);
            cp_async16(sa, &in[(long)grow * 128 + c * 32 + q * 4], grow < n);
        }
        asm volatile("cp.async.commit_group;");
    };

    stage(0, 0);
    stage(1, 1);

#pragma unroll
    for (int c = 0; c < NCHUNK; c++) {
        if (c == NCHUNK - 1) asm volatile("cp.async.wait_group 0;");
        else                 asm volatile("cp.async.wait_group 1;");
        __syncthreads();
        if (c + 2 < NCHUNK) stage(c + 2, (c + 2) % 3);

        const int buf = c % 3;
#pragma unroll
        for (int ks = 0; ks < 4; ks++) {
            uint32_t a0 = f2tf32(hT[buf][lr0][ks * 8 + tig]);
            uint32_t a1 = f2tf32(hT[buf][lr1][ks * 8 + tig]);
            uint32_t a2 = f2tf32(hT[buf][lr0][ks * 8 + tig + 4]);
            uint32_t a3 = f2tf32(hT[buf][lr1][ks * 8 + tig + 4]);

            const uint4* wbase = wf4 + ((c * 4 + ks) * 4 + cw * 2) * 32 + lane;
#pragma unroll
            for (int nbp = 0; nbp < 2; nbp++) {
                uint4 bb = __ldg(wbase + nbp * 32);
                asm volatile(
                    "mma.sync.aligned.m16n8k8.row.col.f32.tf32.tf32.f32 "
                    "{%0,%1,%2,%3}, {%4,%5,%6,%7}, {%8,%9}, {%0,%1,%2,%3};"
                    : "+f"(acc[nbp*2][0]), "+f"(acc[nbp*2][1]),
                      "+f"(acc[nbp*2][2]), "+f"(acc[nbp*2][3])
                    : "r"(a0), "r"(a1), "r"(a2), "r"(a3),
                      "r"(bb.x), "r"(bb.y));
                asm volatile(
                    "mma.sync.aligned.m16n8k8.row.col.f32.tf32.tf32.f32 "
                    "{%0,%1,%2,%3}, {%4,%5,%6,%7}, {%8,%9}, {%0,%1,%2,%3};"
                    : "+f"(acc[nbp*2+1][0]), "+f"(acc[nbp*2+1][1]),
                      "+f"(acc[nbp*2+1][2]), "+f"(acc[nbp*2+1][3])
                    : "r"(a0), "r"(a1), "r"(a2), "r"(a3),
                      "r"(bb.z), "r"(bb.w));
            }
        }
    }

    const int r0 = row0 + lr0;
    const int r1 = row0 + lr1;
    const bool v0 = r0 < n;
    const bool v1 = r1 < n;
#pragma unroll
    for (int nb = 0; nb < 4; nb++) {
        int col = cw * 32 + nb * 8 + tig * 2;
        if (v0) *(__half2*)&out[(long)r0 * 64 + col] = __floats2half2_rn(acc[nb][0], acc[nb][1]);
        if (v1) *(__half2*)&out[(long)r1 * 64 + col] = __floats2half2_rn(acc[nb][2], acc[nb][3]);
    }
}

// ---------------------------------------------------------------------------
// Layers 2-3 GEMM: fp16 m16n8k16, half input (K=64, single stage).
// ---------------------------------------------------------------------------
template <bool HALF_OUT>
__global__ __launch_bounds__(256)
void gemm_fp16_kernel(const __half* __restrict__ in, const uint32_t* __restrict__ wf,
                      void* __restrict__ out_, int n) {
    __shared__ __half hs[64][72];

    const int tid  = threadIdx.x;
    const int w    = tid >> 5;
    const int lane = tid & 31;
    const int grp  = lane >> 2;
    const int tig  = lane & 3;
    const int wg   = w >> 1;
    const int cw   = w & 1;
    const int row0 = blockIdx.x * 64;

    const int lr0 = wg * 16 + grp;
    const int lr1 = lr0 + 8;
    const uint4* wf4 = (const uint4*)wf;

#pragma unroll
    for (int it = 0; it < 2; it++) {
        int idx = tid + it * 256;
        int r = idx >> 3;
        int q = idx & 7;
        int grow = row0 + r;
        uint32_t sa = (uint32_t)__cvta_generic_to_shared(&hs[r][q * 8]);
        cp_async16(sa, &in[(long)grow * 64 + q * 8], grow < n);
    }
    asm volatile("cp.async.commit_group;");

    float acc[4][4];
#pragma unroll
    for (int nb = 0; nb < 4; nb++)
#pragma unroll
        for (int j = 0; j < 4; j++) acc[nb][j] = 0.f;

    asm volatile("cp.async.wait_group 0;");
    __syncthreads();

#pragma unroll
    for (int ks = 0; ks < 4; ks++) {
        uint32_t a0 = *(const uint32_t*)&hs[lr0][ks * 16 + tig * 2];
        uint32_t a1 = *(const uint32_t*)&hs[lr1][ks * 16 + tig * 2];
        uint32_t a2 = *(const uint32_t*)&hs[lr0][ks * 16 + 8 + tig * 2];
        uint32_t a3 = *(const uint32_t*)&hs[lr1][ks * 16 + 8 + tig * 2];

        const uint4* wbase = wf4 + (ks * 4 + cw * 2) * 32 + lane;
#pragma unroll
        for (int nbp = 0; nbp < 2; nbp++) {
            uint4 bb = __ldg(wbase + nbp * 32);
            asm volatile(
                "mma.sync.aligned.m16n8k16.row.col.f32.f16.f16.f32 "
                "{%0,%1,%2,%3}, {%4,%5,%6,%7}, {%8,%9}, {%0,%1,%2,%3};"
                : "+f"(acc[nbp*2][0]), "+f"(acc[nbp*2][1]),
                  "+f"(acc[nbp*2][2]), "+f"(acc[nbp*2][3])
                : "r"(a0), "r"(a1), "r"(a2), "r"(a3),
                  "r"(bb.x), "r"(bb.y));
            asm volatile(
                "mma.sync.aligned.m16n8k16.row.col.f32.f16.f16.f32 "
                "{%0,%1,%2,%3}, {%4,%5,%6,%7}, {%8,%9}, {%0,%1,%2,%3};"
                : "+f"(acc[nbp*2+1][0]), "+f"(acc[nbp*2+1][1]),
                  "+f"(acc[nbp*2+1][2]), "+f"(acc[nbp*2+1][3])
                : "r"(a0), "r"(a1), "r"(a2), "r"(a3),
                  "r"(bb.z), "r"(bb.w));
        }
    }

    const int r0 = row0 + lr0;
    const int r1 = row0 + lr1;
    const bool v0 = r0 < n;
    const bool v1 = r1 < n;
#pragma unroll
    for (int nb = 0; nb < 4; nb++) {
        int col = cw * 32 + nb * 8 + tig * 2;
        if (HALF_OUT) {
            __half* out = (__half*)out_;
            if (v0) *(__half2*)&out[(long)r0 * 64 + col] = __floats2half2_rn(acc[nb][0], acc[nb][1]);
            if (v1) *(__half2*)&out[(long)r1 * 64 + col] = __floats2half2_rn(acc[nb][2], acc[nb][3]);
        } else {
            float* out = (float*)out_;
            if (v0) *(float2*)&out[(long)r0 * 64 + col] = make_float2(acc[nb][0], acc[nb][1]);
            if (v1) *(float2*)&out[(long)r1 * 64 + col] = make_float2(acc[nb][2], acc[nb][3]);
        }
    }
}

// ---------------------------------------------------------------------------
// CSR construction (scan1, scan3, fill)
// ---------------------------------------------------------------------------
__global__ __launch_bounds__(256)
void scan1_kernel(const int* __restrict__ deg, int n,
                  int* __restrict__ incl, int* __restrict__ bsum) {
    __shared__ int s[1024];
    const int base = blockIdx.x * 1024;
    const int t = threadIdx.x;
#pragma unroll
    for (int j = 0; j < 4; j++) {
        int idx = t + j * 256;
        s[idx] = (base + idx < n) ? deg[base + idx] : 0;
    }
    __syncthreads();
    for (int off = 1; off < 1024; off <<= 1) {
        int v[4];
#pragma unroll
        for (int j = 0; j < 4; j++) {
            int idx = t + j * 256;
            v[j] = (idx >= off) ? s[idx - off] : 0;
        }
        __syncthreads();
#pragma unroll
        for (int j = 0; j < 4; j++) s[t + j * 256] += v[j];
        __syncthreads();
    }
#pragma unroll
    for (int j = 0; j < 4; j++) {
        int idx = t + j * 256;
        if (base + idx < n) incl[base + idx] = s[idx];
    }
    if (t == 0) bsum[blockIdx.x] = s[1023];
}

__global__ __launch_bounds__(256)
void scan3_kernel(const int* __restrict__ incl, int* __restrict__ deg,
                  const int* __restrict__ bsum, int nb, int n, int E,
                  int* __restrict__ rp, int* __restrict__ cursor) {
    __shared__ int s[128];
    const int t = threadIdx.x;
    if (t < 128) s[t] = (t < nb) ? bsum[t] : 0;
    __syncthreads();
    for (int off = 1; off < 128; off <<= 1) {
        int v = 0;
        if (t < 128 && t >= off) v = s[t - off];
        __syncthreads();
        if (t < 128) s[t] += v;
        __syncthreads();
    }
    int i = blockIdx.x * blockDim.x + t;
    if (i >= n) return;
    int b = i >> 10;
    int add = b ? s[b - 1] : 0;
    int excl = incl[i] - deg[i] + add;
    rp[i] = excl;
    cursor[i] = excl;
    deg[i] = 0;
    if (i == n - 1) rp[n] = E;
}

// fill: 4 edges/thread via int4 loads (src and dst streams).
__global__ __launch_bounds__(256)
void fill_kernel(const int* __restrict__ ei, int E,
                 int* __restrict__ cursor, int* __restrict__ csr) {
    int e0 = (blockIdx.x * 256 + threadIdx.x) * 4;
    if (e0 + 3 < E && (E & 3) == 0) {
        int4 s4 = *(const int4*)&ei[e0];
        int4 d4 = *(const int4*)&ei[E + e0];
        csr[atomicAdd(&cursor[d4.x], 1)] = s4.x;
        csr[atomicAdd(&cursor[d4.y], 1)] = s4.y;
        csr[atomicAdd(&cursor[d4.z], 1)] = s4.z;
        csr[atomicAdd(&cursor[d4.w], 1)] = s4.w;
    } else {
        for (int j = 0; j < 4; j++) {
            int e = e0 + j;
            if (e < E) {
                int src = ei[e];
                int dst = ei[E + e];
                csr[atomicAdd(&cursor[dst], 1)] = src;
            }
        }
    }
}

// ---------------------------------------------------------------------------
// Gather-reduce (fp16 t) + bias + relu -> fp16 h
// ---------------------------------------------------------------------------
__global__ __launch_bounds__(256)
void gather_h2_kernel(const int* __restrict__ rp, const int* __restrict__ csr,
                      const __half* __restrict__ t, const float* __restrict__ bias,
                      __half* __restrict__ out, int n) {
    int warp = (blockIdx.x * blockDim.x + threadIdx.x) >> 5;
    int lane = threadIdx.x & 31;
    if (warp >= n) return;

    int s0 = rp[warp];
    int s1 = rp[warp + 1];
    const __half2* tp = (const __half2*)t;

    float ax = 0.f, ay = 0.f, bx = 0.f, by = 0.f;
    int e = s0;
    for (; e + 15 < s1; e += 16) {
        int idx[16];
#pragma unroll
        for (int j = 0; j < 16; j++) idx[j] = __ldg(&csr[e + j]);
        float2 v[16];
#pragma unroll
        for (int j = 0; j < 16; j++)
            v[j] = __half22float2(tp[(long)idx[j] * 32 + lane]);
#pragma unroll
        for (int j = 0; j < 16; j += 4) {
            ax += v[j + 0].x + v[j + 2].x;  ay += v[j + 0].y + v[j + 2].y;
            bx += v[j + 1].x + v[j + 3].x;  by += v[j + 1].y + v[j + 3].y;
        }
    }
    for (; e + 3 < s1; e += 4) {
        int i0 = __ldg(&csr[e + 0]);
        int i1 = __ldg(&csr[e + 1]);
        int i2 = __ldg(&csr[e + 2]);
        int i3 = __ldg(&csr[e + 3]);
        float2 v0 = __half22float2(tp[(long)i0 * 32 + lane]);
        float2 v1 = __half22float2(tp[(long)i1 * 32 + lane]);
        float2 v2 = __half22float2(tp[(long)i2 * 32 + lane]);
        float2 v3 = __half22float2(tp[(long)i3 * 32 + lane]);
        ax += v0.x + v2.x;  ay += v0.y + v2.y;
        bx += v1.x + v3.x;  by += v1.y + v3.y;
    }
    for (; e < s1; e++) {
        int i0 = __ldg(&csr[e]);
        float2 v = __half22float2(tp[(long)i0 * 32 + lane]);
        ax += v.x; ay += v.y;
    }
    ax += bx; ay += by;

    float2 bb = *(const float2*)&bias[lane * 2];
    float rx = fmaxf(ax + bb.x, 0.f);
    float ry = fmaxf(ay + bb.y, 0.f);
    ((__half2*)out)[(long)warp * 32 + lane] = __floats2half2_rn(rx, ry);
}

// ---------------------------------------------------------------------------
// Final gather (fp32 t) + bias + sigmoid
// ---------------------------------------------------------------------------
__global__ __launch_bounds__(256)
void gather_f32_sig_kernel(const int* __restrict__ rp, const int* __restrict__ csr,
                           const float* __restrict__ t, const float* __restrict__ bias,
                           float* __restrict__ out, int n) {
    int warp = (blockIdx.x * blockDim.x + threadIdx.x) >> 5;
    int lane = threadIdx.x & 31;
    if (warp >= n) return;

    int s0 = rp[warp];
    int s1 = rp[warp + 1];

    float ax = 0.f, ay = 0.f, bx = 0.f, by = 0.f;
    int e = s0;
    for (; e + 7 < s1; e += 8) {
        int idx[8];
#pragma unroll
        for (int j = 0; j < 8; j++) idx[j] = __ldg(&csr[e + j]);
        float2 v[8];
#pragma unroll
        for (int j = 0; j < 8; j++)
            v[j] = *(const float2*)&t[(long)idx[j] * 64 + lane * 2];
#pragma unroll
        for (int j = 0; j < 8; j += 4) {
            ax += v[j + 0].x + v[j + 2].x;  ay += v[j + 0].y + v[j + 2].y;
            bx += v[j + 1].x + v[j + 3].x;  by += v[j + 1].y + v[j + 3].y;
        }
    }
    for (; e < s1; e++) {
        int i0 = __ldg(&csr[e]);
        float2 v = *(const float2*)&t[(long)i0 * 64 + lane * 2];
        ax += v.x; ay += v.y;
    }
    ax += bx; ay += by;

    float2 bb = *(const float2*)&bias[lane * 2];
    ax += bb.x; ay += bb.y;
    float2 r;
    r.x = 1.f / (1.f + __expf(-ax));
    r.y = 1.f / (1.f + __expf(-ay));
    *(float2*)&out[(long)warp * 64 + lane * 2] = r;
}

extern "C" void kernel_launch(void* const* d_in, const int* in_sizes, int n_in,
                              void* d_out, int out_size) {
    const float* x  = (const float*)d_in[0];
    const int*   ei = (const int*)d_in[1];
    const float* W1 = (const float*)d_in[2];
    const float* b1 = (const float*)d_in[3];
    const float* W2 = (const float*)d_in[4];
    const float* b2 = (const float*)d_in[5];
    const float* W3 = (const float*)d_in[6];
    const float* b3 = (const float*)d_in[7];
    float* out = (float*)d_out;

    const int N = in_sizes[0] / 128;
    const int E = in_sizes[1] / 2;

    __half *t16a, *t16b;
    float *t32, *hbuf;
    int *deg, *incl, *rp, *cursor, *bsum, *csr;
    uint32_t* wf;
    cudaGetSymbolAddress((void**)&t16a,   g_t16a);
    cudaGetSymbolAddress((void**)&t16b,   g_t16b);
    cudaGetSymbolAddress((void**)&t32,    g_t32);
    cudaGetSymbolAddress((void**)&hbuf,   g_h);
    cudaGetSymbolAddress((void**)&deg,    g_deg);
    cudaGetSymbolAddress((void**)&incl,   g_incl);
    cudaGetSymbolAddress((void**)&rp,     g_rp);
    cudaGetSymbolAddress((void**)&cursor, g_cursor);
    cudaGetSymbolAddress((void**)&bsum,   g_bsum);
    cudaGetSymbolAddress((void**)&csr,    g_csr);
    cudaGetSymbolAddress((void**)&wf,     g_wf);

    __half* h16a = (__half*)hbuf;
    __half* h16b = (__half*)hbuf + (long)NMAX * 64;

    const int nb_scan = (N + 1023) / 1024;
    const int nblk  = (N + 255) / 256;
    const int eblk4 = (E + 1023) / 1024;   // 4 edges/thread
    const int gb64  = (N + 63) / 64;
    const int wb    = (N + 7) / 8;

    hist_wprep_kernel<<<eblk4 + 3, 256>>>(ei, E, deg, W1, W2, W3, wf);       // 1
    scan1_kernel<<<nb_scan, 256>>>(deg, N, incl, bsum);                      // 2
    scan3_kernel<<<nblk, 256>>>(incl, deg, bsum, nb_scan, N, E, rp, cursor); // 3
    fill_kernel<<<eblk4, 256>>>(ei, E, cursor, csr);                         // 4 (profiled)
    gemm_tf32_kernel<<<gb64, 256>>>(x, wf, t16a, N);                         // 5

    gather_h2_kernel<<<wb, 256>>>(rp, csr, t16a, b1, h16a, N);               // 6
    gemm_fp16_kernel<true><<<gb64, 256>>>(h16a, wf + 8192, t16b, N);         // 7
    gather_h2_kernel<<<wb, 256>>>(rp, csr, t16b, b2, h16b, N);               // 8
    gemm_fp16_kernel<false><<<gb64, 256>>>(h16b, wf + 10240, t32, N);        // 9
    gather_f32_sig_kernel<<<wb, 256>>>(rp, csr, t32, b3, out, N);            // 10
}

// round 16
// speedup vs baseline: 1.0102x; 1.0080x over previous
#include <cuda_runtime.h>
#include <cuda_fp16.h>
#include <math.h>
#include <stdint.h>

#define NMAX 100000
#define EMAX 2000000

// Scratch (alloc-free: __device__ globals, zero-initialized at load)
__device__ __half g_t16a[NMAX * 64];   // layer-1 linear output (fp16)
__device__ __half g_t16b[NMAX * 64];   // layer-2 linear output (fp16)
__device__ float  g_t32[NMAX * 64];    // layer-3 linear output (fp32)
__device__ float  g_h[NMAX * 64];      // reused as TWO half buffers (act1, act2)
__device__ int    g_deg[NMAX];         // self-cleaning (scan3 re-zeroes)
__device__ int    g_incl[NMAX];
__device__ int    g_rp[NMAX + 1];
__device__ int    g_cursor[NMAX];
__device__ int    g_bsum[128];
__device__ int    g_csr[EMAX];
// W1 tf32 fragments (8192 u32) + W2 fp16 (2048) + W3 fp16 (2048)
__device__ __align__(16) uint32_t g_wf[8192 + 2048 + 2048];

__device__ __forceinline__ uint32_t f2tf32(float f) {
    uint32_t r;
    asm("cvt.rna.tf32.f32 %0, %1;" : "=r"(r) : "f"(f));
    return r;
}

__device__ __forceinline__ void cp_async16(uint32_t saddr, const void* gptr, bool valid) {
    int sz = valid ? 16 : 0;
    asm volatile("cp.async.cg.shared.global [%0], [%1], 16, %2;"
                 :: "r"(saddr), "l"(gptr), "r"(sz));
}

// ---------------------------------------------------------------------------
// hist + W prep merged. Block 0: W1 tf32. Blocks 1,2: W2/W3 fp16 fragments.
// Rest: degree histogram, 4 edges/thread via int4 loads.
// ---------------------------------------------------------------------------
__global__ __launch_bounds__(256)
void hist_wprep_kernel(const int* __restrict__ ei, int E, int* __restrict__ deg,
                       const float* __restrict__ W1, const float* __restrict__ W2,
                       const float* __restrict__ W3, uint32_t* __restrict__ wf) {
    if (blockIdx.x == 0) {
        for (int idx = threadIdx.x; idx < 128 * 64; idx += 256) {
            int k  = idx >> 6;
            int nn = idx & 63;
            int ks = k >> 3, kk = k & 7;
            int ch = kk >> 2, c = kk & 3;
            int nb = nn >> 3, ng = nn & 7;
            int lane = ng * 4 + c;
            int pos = (((ks * 4 + (nb >> 1)) * 32) + lane) * 4 + (nb & 1) * 2 + ch;
            wf[pos] = f2tf32(W1[idx]);
        }
    } else if (blockIdx.x <= 2) {
        const float* W = (blockIdx.x == 1) ? W2 : W3;
        uint32_t* dst = wf + 8192 + (blockIdx.x - 1) * 2048;
        for (int u = threadIdx.x; u < 2048; u += 256) {
            int reg  = u & 1;
            int lane = (u >> 1) & 31;
            int nb   = (u >> 6) & 7;
            int ks16 = u >> 9;
            int tig = lane & 3, grp = lane >> 2;
            int k0 = ks16 * 16 + reg * 8 + tig * 2;
            int n  = nb * 8 + grp;
            __half2 hv = __floats2half2_rn(W[k0 * 64 + n], W[(k0 + 1) * 64 + n]);
            int pos = (((ks16 * 4 + (nb >> 1)) * 32) + lane) * 4 + (nb & 1) * 2 + reg;
            dst[pos] = *(uint32_t*)&hv;
        }
    } else {
        int e0 = ((blockIdx.x - 3) * 256 + threadIdx.x) * 4;
        if (e0 + 3 < E && (E & 3) == 0) {
            int4 d4 = *(const int4*)&ei[E + e0];
            atomicAdd(&deg[d4.x], 1);
            atomicAdd(&deg[d4.y], 1);
            atomicAdd(&deg[d4.z], 1);
            atomicAdd(&deg[d4.w], 1);
        } else {
            for (int j = 0; j < 4; j++) {
                int e = e0 + j;
                if (e < E) atomicAdd(&deg[ei[E + e]], 1);
            }
        }
    }
}

// ---------------------------------------------------------------------------
// FUSED: csr-fill (blocks [0, fillBlocks)) + layer-1 tf32 GEMM (rest).
// The two workloads are independent; fusing them overlaps an L2-scatter
// (issue-starved) with a tensor/DRAM GEMM inside one launch.
// ---------------------------------------------------------------------------
__global__ __launch_bounds__(256)
void fill_gemm1_kernel(const int* __restrict__ ei, int E,
                       int* __restrict__ cursor, int* __restrict__ csr,
                       int fillBlocks,
                       const float* __restrict__ in, const uint32_t* __restrict__ wf,
                       __half* __restrict__ out, int n) {
    __shared__ float hT[3][64][36];

    if (blockIdx.x < fillBlocks) {
        // ---- fill body: 4 edges/thread via int4 ----
        int e0 = (blockIdx.x * 256 + threadIdx.x) * 4;
        if (e0 + 3 < E && (E & 3) == 0) {
            int4 s4 = *(const int4*)&ei[e0];
            int4 d4 = *(const int4*)&ei[E + e0];
            csr[atomicAdd(&cursor[d4.x], 1)] = s4.x;
            csr[atomicAdd(&cursor[d4.y], 1)] = s4.y;
            csr[atomicAdd(&cursor[d4.z], 1)] = s4.z;
            csr[atomicAdd(&cursor[d4.w], 1)] = s4.w;
        } else {
            for (int j = 0; j < 4; j++) {
                int e = e0 + j;
                if (e < E) {
                    int src = ei[e];
                    int dst = ei[E + e];
                    csr[atomicAdd(&cursor[dst], 1)] = src;
                }
            }
        }
        return;
    }

    // ---- GEMM body: tf32, K=128, 64 rows/block, 3-stage cp.async ----
    constexpr int NCHUNK = 4;
    const int bid  = blockIdx.x - fillBlocks;
    const int tid  = threadIdx.x;
    const int w    = tid >> 5;
    const int lane = tid & 31;
    const int grp  = lane >> 2;
    const int tig  = lane & 3;
    const int wg   = w >> 1;
    const int cw   = w & 1;
    const int row0 = bid * 64;

    const int lr0 = wg * 16 + grp;
    const int lr1 = lr0 + 8;
    const uint4* wf4 = (const uint4*)wf;

    float acc[4][4];
#pragma unroll
    for (int nb = 0; nb < 4; nb++)
#pragma unroll
        for (int j = 0; j < 4; j++) acc[nb][j] = 0.f;

    auto stage = [&](int c, int buf) {
#pragma unroll
        for (int it = 0; it < 2; it++) {
            int idx = tid + it * 256;
            int r = idx >> 3;
            int q = idx & 7;
            int grow = row0 + r;
            uint32_t sa = (uint32_t)__cvta_generic_to_shared(&hT[buf][r][q * 4]);
            cp_async16(sa, &in[(long)grow * 128 + c * 32 + q * 4], grow < n);
        }
        asm volatile("cp.async.commit_group;");
    };

    stage(0, 0);
    stage(1, 1);

#pragma unroll
    for (int c = 0; c < NCHUNK; c++) {
        if (c == NCHUNK - 1) asm volatile("cp.async.wait_group 0;");
        else                 asm volatile("cp.async.wait_group 1;");
        __syncthreads();
        if (c + 2 < NCHUNK) stage(c + 2, (c + 2) % 3);

        const int buf = c % 3;
#pragma unroll
        for (int ks = 0; ks < 4; ks++) {
            uint32_t a0 = f2tf32(hT[buf][lr0][ks * 8 + tig]);
            uint32_t a1 = f2tf32(hT[buf][lr1][ks * 8 + tig]);
            uint32_t a2 = f2tf32(hT[buf][lr0][ks * 8 + tig + 4]);
            uint32_t a3 = f2tf32(hT[buf][lr1][ks * 8 + tig + 4]);

            const uint4* wbase = wf4 + ((c * 4 + ks) * 4 + cw * 2) * 32 + lane;
#pragma unroll
            for (int nbp = 0; nbp < 2; nbp++) {
                uint4 bb = __ldg(wbase + nbp * 32);
                asm volatile(
                    "mma.sync.aligned.m16n8k8.row.col.f32.tf32.tf32.f32 "
                    "{%0,%1,%2,%3}, {%4,%5,%6,%7}, {%8,%9}, {%0,%1,%2,%3};"
                    : "+f"(acc[nbp*2][0]), "+f"(acc[nbp*2][1]),
                      "+f"(acc[nbp*2][2]), "+f"(acc[nbp*2][3])
                    : "r"(a0), "r"(a1), "r"(a2), "r"(a3),
                      "r"(bb.x), "r"(bb.y));
                asm volatile(
                    "mma.sync.aligned.m16n8k8.row.col.f32.tf32.tf32.f32 "
                    "{%0,%1,%2,%3}, {%4,%5,%6,%7}, {%8,%9}, {%0,%1,%2,%3};"
                    : "+f"(acc[nbp*2+1][0]), "+f"(acc[nbp*2+1][1]),
                      "+f"(acc[nbp*2+1][2]), "+f"(acc[nbp*2+1][3])
                    : "r"(a0), "r"(a1), "r"(a2), "r"(a3),
                      "r"(bb.z), "r"(bb.w));
            }
        }
    }

    const int r0 = row0 + lr0;
    const int r1 = row0 + lr1;
    const bool v0 = r0 < n;
    const bool v1 = r1 < n;
#pragma unroll
    for (int nb = 0; nb < 4; nb++) {
        int col = cw * 32 + nb * 8 + tig * 2;
        if (v0) *(__half2*)&out[(long)r0 * 64 + col] = __floats2half2_rn(acc[nb][0], acc[nb][1]);
        if (v1) *(__half2*)&out[(long)r1 * 64 + col] = __floats2half2_rn(acc[nb][2], acc[nb][3]);
    }
}

// ---------------------------------------------------------------------------
// Layers 2-3 GEMM: fp16 m16n8k16, half input (K=64, single stage).
// ---------------------------------------------------------------------------
template <bool HALF_OUT>
__global__ __launch_bounds__(256)
void gemm_fp16_kernel(const __half* __restrict__ in, const uint32_t* __restrict__ wf,
                      void* __restrict__ out_, int n) {
    __shared__ __half hs[64][72];

    const int tid  = threadIdx.x;
    const int w    = tid >> 5;
    const int lane = tid & 31;
    const int grp  = lane >> 2;
    const int tig  = lane & 3;
    const int wg   = w >> 1;
    const int cw   = w & 1;
    const int row0 = blockIdx.x * 64;

    const int lr0 = wg * 16 + grp;
    const int lr1 = lr0 + 8;
    const uint4* wf4 = (const uint4*)wf;

#pragma unroll
    for (int it = 0; it < 2; it++) {
        int idx = tid + it * 256;
        int r = idx >> 3;
        int q = idx & 7;
        int grow = row0 + r;
        uint32_t sa = (uint32_t)__cvta_generic_to_shared(&hs[r][q * 8]);
        cp_async16(sa, &in[(long)grow * 64 + q * 8], grow < n);
    }
    asm volatile("cp.async.commit_group;");

    float acc[4][4];
#pragma unroll
    for (int nb = 0; nb < 4; nb++)
#pragma unroll
        for (int j = 0; j < 4; j++) acc[nb][j] = 0.f;

    asm volatile("cp.async.wait_group 0;");
    __syncthreads();

#pragma unroll
    for (int ks = 0; ks < 4; ks++) {
        uint32_t a0 = *(const uint32_t*)&hs[lr0][ks * 16 + tig * 2];
        uint32_t a1 = *(const uint32_t*)&hs[lr1][ks * 16 + tig * 2];
        uint32_t a2 = *(const uint32_t*)&hs[lr0][ks * 16 + 8 + tig * 2];
        uint32_t a3 = *(const uint32_t*)&hs[lr1][ks * 16 + 8 + tig * 2];

        const uint4* wbase = wf4 + (ks * 4 + cw * 2) * 32 + lane;
#pragma unroll
        for (int nbp = 0; nbp < 2; nbp++) {
            uint4 bb = __ldg(wbase + nbp * 32);
            asm volatile(
                "mma.sync.aligned.m16n8k16.row.col.f32.f16.f16.f32 "
                "{%0,%1,%2,%3}, {%4,%5,%6,%7}, {%8,%9}, {%0,%1,%2,%3};"
                : "+f"(acc[nbp*2][0]), "+f"(acc[nbp*2][1]),
                  "+f"(acc[nbp*2][2]), "+f"(acc[nbp*2][3])
                : "r"(a0), "r"(a1), "r"(a2), "r"(a3),
                  "r"(bb.x), "r"(bb.y));
            asm volatile(
                "mma.sync.aligned.m16n8k16.row.col.f32.f16.f16.f32 "
                "{%0,%1,%2,%3}, {%4,%5,%6,%7}, {%8,%9}, {%0,%1,%2,%3};"
                : "+f"(acc[nbp*2+1][0]), "+f"(acc[nbp*2+1][1]),
                  "+f"(acc[nbp*2+1][2]), "+f"(acc[nbp*2+1][3])
                : "r"(a0), "r"(a1), "r"(a2), "r"(a3),
                  "r"(bb.z), "r"(bb.w));
        }
    }

    const int r0 = row0 + lr0;
    const int r1 = row0 + lr1;
    const bool v0 = r0 < n;
    const bool v1 = r1 < n;
#pragma unroll
    for (int nb = 0; nb < 4; nb++) {
        int col = cw * 32 + nb * 8 + tig * 2;
        if (HALF_OUT) {
            __half* out = (__half*)out_;
            if (v0) *(__half2*)&out[(long)r0 * 64 + col] = __floats2half2_rn(acc[nb][0], acc[nb][1]);
            if (v1) *(__half2*)&out[(long)r1 * 64 + col] = __floats2half2_rn(acc[nb][2], acc[nb][3]);
        } else {
            float* out = (float*)out_;
            if (v0) *(float2*)&out[(long)r0 * 64 + col] = make_float2(acc[nb][0], acc[nb][1]);
            if (v1) *(float2*)&out[(long)r1 * 64 + col] = make_float2(acc[nb][2], acc[nb][3]);
        }
    }
}

// ---------------------------------------------------------------------------
// CSR scans
// ---------------------------------------------------------------------------
__global__ __launch_bounds__(256)
void scan1_kernel(const int* __restrict__ deg, int n,
                  int* __restrict__ incl, int* __restrict__ bsum) {
    __shared__ int s[1024];
    const int base = blockIdx.x * 1024;
    const int t = threadIdx.x;
#pragma unroll
    for (int j = 0; j < 4; j++) {
        int idx = t + j * 256;
        s[idx] = (base + idx < n) ? deg[base + idx] : 0;
    }
    __syncthreads();
    for (int off = 1; off < 1024; off <<= 1) {
        int v[4];
#pragma unroll
        for (int j = 0; j < 4; j++) {
            int idx = t + j * 256;
            v[j] = (idx >= off) ? s[idx - off] : 0;
        }
        __syncthreads();
#pragma unroll
        for (int j = 0; j < 4; j++) s[t + j * 256] += v[j];
        __syncthreads();
    }
#pragma unroll
    for (int j = 0; j < 4; j++) {
        int idx = t + j * 256;
        if (base + idx < n) incl[base + idx] = s[idx];
    }
    if (t == 0) bsum[blockIdx.x] = s[1023];
}

__global__ __launch_bounds__(256)
void scan3_kernel(const int* __restrict__ incl, int* __restrict__ deg,
                  const int* __restrict__ bsum, int nb, int n, int E,
                  int* __restrict__ rp, int* __restrict__ cursor) {
    __shared__ int s[128];
    const int t = threadIdx.x;
    if (t < 128) s[t] = (t < nb) ? bsum[t] : 0;
    __syncthreads();
    for (int off = 1; off < 128; off <<= 1) {
        int v = 0;
        if (t < 128 && t >= off) v = s[t - off];
        __syncthreads();
        if (t < 128) s[t] += v;
        __syncthreads();
    }
    int i = blockIdx.x * blockDim.x + t;
    if (i >= n) return;
    int b = i >> 10;
    int add = b ? s[b - 1] : 0;
    int excl = incl[i] - deg[i] + add;
    rp[i] = excl;
    cursor[i] = excl;
    deg[i] = 0;
    if (i == n - 1) rp[n] = E;
}

// ---------------------------------------------------------------------------
// Gather-reduce (fp16 t) + bias + relu -> fp16 h
// ---------------------------------------------------------------------------
__global__ __launch_bounds__(256)
void gather_h2_kernel(const int* __restrict__ rp, const int* __restrict__ csr,
                      const __half* __restrict__ t, const float* __restrict__ bias,
                      __half* __restrict__ out, int n) {
    int warp = (blockIdx.x * blockDim.x + threadIdx.x) >> 5;
    int lane = threadIdx.x & 31;
    if (warp >= n) return;

    int s0 = rp[warp];
    int s1 = rp[warp + 1];
    const __half2* tp = (const __half2*)t;

    float ax = 0.f, ay = 0.f, bx = 0.f, by = 0.f;
    int e = s0;
    for (; e + 15 < s1; e += 16) {
        int idx[16];
#pragma unroll
        for (int j = 0; j < 16; j++) idx[j] = __ldg(&csr[e + j]);
        float2 v[16];
#pragma unroll
        for (int j = 0; j < 16; j++)
            v[j] = __half22float2(tp[(long)idx[j] * 32 + lane]);
#pragma unroll
        for (int j = 0; j < 16; j += 4) {
            ax += v[j + 0].x + v[j + 2].x;  ay += v[j + 0].y + v[j + 2].y;
            bx += v[j + 1].x + v[j + 3].x;  by += v[j + 1].y + v[j + 3].y;
        }
    }
    for (; e + 3 < s1; e += 4) {
        int i0 = __ldg(&csr[e + 0]);
        int i1 = __ldg(&csr[e + 1]);
        int i2 = __ldg(&csr[e + 2]);
        int i3 = __ldg(&csr[e + 3]);
        float2 v0 = __half22float2(tp[(long)i0 * 32 + lane]);
        float2 v1 = __half22float2(tp[(long)i1 * 32 + lane]);
        float2 v2 = __half22float2(tp[(long)i2 * 32 + lane]);
        float2 v3 = __half22float2(tp[(long)i3 * 32 + lane]);
        ax += v0.x + v2.x;  ay += v0.y + v2.y;
        bx += v1.x + v3.x;  by += v1.y + v3.y;
    }
    for (; e < s1; e++) {
        int i0 = __ldg(&csr[e]);
        float2 v = __half22float2(tp[(long)i0 * 32 + lane]);
        ax += v.x; ay += v.y;
    }
    ax += bx; ay += by;

    float2 bb = *(const float2*)&bias[lane * 2];
    float rx = fmaxf(ax + bb.x, 0.f);
    float ry = fmaxf(ay + bb.y, 0.f);
    ((__half2*)out)[(long)warp * 32 + lane] = __floats2half2_rn(rx, ry);
}

// ---------------------------------------------------------------------------
// Final gather (fp32 t) + bias + sigmoid
// ---------------------------------------------------------------------------
__global__ __launch_bounds__(256)
void gather_f32_sig_kernel(const int* __restrict__ rp, const int* __restrict__ csr,
                           const float* __restrict__ t, const float* __restrict__ bias,
                           float* __restrict__ out, int n) {
    int warp = (blockIdx.x * blockDim.x + threadIdx.x) >> 5;
    int lane = threadIdx.x & 31;
    if (warp >= n) return;

    int s0 = rp[warp];
    int s1 = rp[warp + 1];

    float ax = 0.f, ay = 0.f, bx = 0.f, by = 0.f;
    int e = s0;
    for (; e + 7 < s1; e += 8) {
        int idx[8];
#pragma unroll
        for (int j = 0; j < 8; j++) idx[j] = __ldg(&csr[e + j]);
        float2 v[8];
#pragma unroll
        for (int j = 0; j < 8; j++)
            v[j] = *(const float2*)&t[(long)idx[j] * 64 + lane * 2];
#pragma unroll
        for (int j = 0; j < 8; j += 4) {
            ax += v[j + 0].x + v[j + 2].x;  ay += v[j + 0].y + v[j + 2].y;
            bx += v[j + 1].x + v[j + 3].x;  by += v[j + 1].y + v[j + 3].y;
        }
    }
    for (; e < s1; e++) {
        int i0 = __ldg(&csr[e]);
        float2 v = *(const float2*)&t[(long)i0 * 64 + lane * 2];
        ax += v.x; ay += v.y;
    }
    ax += bx; ay += by;

    float2 bb = *(const float2*)&bias[lane * 2];
    ax += bb.x; ay += bb.y;
    float2 r;
    r.x = 1.f / (1.f + __expf(-ax));
    r.y = 1.f / (1.f + __expf(-ay));
    *(float2*)&out[(long)warp * 64 + lane * 2] = r;
}

extern "C" void kernel_launch(void* const* d_in, const int* in_sizes, int n_in,
                              void* d_out, int out_size) {
    const float* x  = (const float*)d_in[0];
    const int*   ei = (const int*)d_in[1];
    const float* W1 = (const float*)d_in[2];
    const float* b1 = (const float*)d_in[3];
    const float* W2 = (const float*)d_in[4];
    const float* b2 = (const float*)d_in[5];
    const float* W3 = (const float*)d_in[6];
    const float* b3 = (const float*)d_in[7];
    float* out = (float*)d_out;

    const int N = in_sizes[0] / 128;
    const int E = in_sizes[1] / 2;

    __half *t16a, *t16b;
    float *t32, *hbuf;
    int *deg, *incl, *rp, *cursor, *bsum, *csr;
    uint32_t* wf;
    cudaGetSymbolAddress((void**)&t16a,   g_t16a);
    cudaGetSymbolAddress((void**)&t16b,   g_t16b);
    cudaGetSymbolAddress((void**)&t32,    g_t32);
    cudaGetSymbolAddress((void**)&hbuf,   g_h);
    cudaGetSymbolAddress((void**)&deg,    g_deg);
    cudaGetSymbolAddress((void**)&incl,   g_incl);
    cudaGetSymbolAddress((void**)&rp,     g_rp);
    cudaGetSymbolAddress((void**)&cursor, g_cursor);
    cudaGetSymbolAddress((void**)&bsum,   g_bsum);
    cudaGetSymbolAddress((void**)&csr,    g_csr);
    cudaGetSymbolAddress((void**)&wf,     g_wf);

    __half* h16a = (__half*)hbuf;
    __half* h16b = (__half*)hbuf + (long)NMAX * 64;

    const int nb_scan = (N + 1023) / 1024;
    const int nblk  = (N + 255) / 256;
    const int eblk4 = (E + 1023) / 1024;   // 4 edges/thread
    const int gb64  = (N + 63) / 64;
    const int wb    = (N + 7) / 8;

    hist_wprep_kernel<<<eblk4 + 3, 256>>>(ei, E, deg, W1, W2, W3, wf);       // 1
    scan1_kernel<<<nb_scan, 256>>>(deg, N, incl, bsum);                      // 2
    scan3_kernel<<<nblk, 256>>>(incl, deg, bsum, nb_scan, N, E, rp, cursor); // 3
    // 4 (profiled): fill + gemm1 fused, overlapped in one launch
    fill_gemm1_kernel<<<eblk4 + gb64, 256>>>(ei, E, cursor, csr, eblk4,
                                             x, wf, t16a, N);

    gather_h2_kernel<<<wb, 256>>>(rp, csr, t16a, b1, h16a, N);               // 5
    gemm_fp16_kernel<true><<<gb64, 256>>>(h16a, wf + 8192, t16b, N);         // 6
    gather_h2_kernel<<<wb, 256>>>(rp, csr, t16b, b2, h16b, N);               // 7
    gemm_fp16_kernel<false><<<gb64, 256>>>(h16b, wf + 10240, t32, N);        // 8
    gather_f32_sig_kernel<<<wb, 256>>>(rp, csr, t32, b3, out, N);            // 9
}

// round 17
// speedup vs baseline: 1.0586x; 1.0479x over previous
#include <cuda_runtime.h>
#include <cuda_fp16.h>
#include <math.h>
#include <stdint.h>

#define NMAX 100000
#define EMAX 2000000

// Scratch (alloc-free: __device__ globals, zero-initialized at load)
__device__ __half g_t16a[NMAX * 64];   // layer-1 linear output (fp16)
__device__ __half g_t16b[NMAX * 64];   // layer-2 linear output (fp16)
__device__ float  g_t32[NMAX * 64];    // layer-3 linear output (fp32)
__device__ float  g_h[NMAX * 64];      // reused as TWO half buffers (act1, act2)
__device__ int    g_deg[NMAX];         // self-cleaning (scan3 re-zeroes)
__device__ int    g_incl[NMAX];
__device__ int    g_rp[NMAX + 1];
__device__ int    g_cursor[NMAX];
__device__ int    g_bsum[128];
__device__ int    g_csr[EMAX];
// W1 tf32 fragments (8192 u32) + W2 fp16 (2048) + W3 fp16 (2048)
__device__ __align__(16) uint32_t g_wf[8192 + 2048 + 2048];

__device__ __forceinline__ uint32_t f2tf32(float f) {
    uint32_t r;
    asm("cvt.rna.tf32.f32 %0, %1;" : "=r"(r) : "f"(f));
    return r;
}

__device__ __forceinline__ void cp_async16(uint32_t saddr, const void* gptr, bool valid) {
    int sz = valid ? 16 : 0;
    asm volatile("cp.async.cg.shared.global [%0], [%1], 16, %2;"
                 :: "r"(saddr), "l"(gptr), "r"(sz));
}

// ---------------------------------------------------------------------------
// hist + W prep merged. Block 0: W1 tf32. Blocks 1,2: W2/W3 fp16 fragments.
// Rest: degree histogram, 4 edges/thread via int4 loads.
// ---------------------------------------------------------------------------
__global__ __launch_bounds__(256)
void hist_wprep_kernel(const int* __restrict__ ei, int E, int* __restrict__ deg,
                       const float* __restrict__ W1, const float* __restrict__ W2,
                       const float* __restrict__ W3, uint32_t* __restrict__ wf) {
    if (blockIdx.x == 0) {
        for (int idx = threadIdx.x; idx < 128 * 64; idx += 256) {
            int k  = idx >> 6;
            int nn = idx & 63;
            int ks = k >> 3, kk = k & 7;
            int ch = kk >> 2, c = kk & 3;
            int nb = nn >> 3, ng = nn & 7;
            int lane = ng * 4 + c;
            int pos = (((ks * 4 + (nb >> 1)) * 32) + lane) * 4 + (nb & 1) * 2 + ch;
            wf[pos] = f2tf32(W1[idx]);
        }
    } else if (blockIdx.x <= 2) {
        const float* W = (blockIdx.x == 1) ? W2 : W3;
        uint32_t* dst = wf + 8192 + (blockIdx.x - 1) * 2048;
        for (int u = threadIdx.x; u < 2048; u += 256) {
            int reg  = u & 1;
            int lane = (u >> 1) & 31;
            int nb   = (u >> 6) & 7;
            int ks16 = u >> 9;
            int tig = lane & 3, grp = lane >> 2;
            int k0 = ks16 * 16 + reg * 8 + tig * 2;
            int n  = nb * 8 + grp;
            __half2 hv = __floats2half2_rn(W[k0 * 64 + n], W[(k0 + 1) * 64 + n]);
            int pos = (((ks16 * 4 + (nb >> 1)) * 32) + lane) * 4 + (nb & 1) * 2 + reg;
            dst[pos] = *(uint32_t*)&hv;
        }
    } else {
        int e0 = ((blockIdx.x - 3) * 256 + threadIdx.x) * 4;
        if (e0 + 3 < E && (E & 3) == 0) {
            int4 d4 = *(const int4*)&ei[E + e0];
            atomicAdd(&deg[d4.x], 1);
            atomicAdd(&deg[d4.y], 1);
            atomicAdd(&deg[d4.z], 1);
            atomicAdd(&deg[d4.w], 1);
        } else {
            for (int j = 0; j < 4; j++) {
                int e = e0 + j;
                if (e < E) atomicAdd(&deg[ei[E + e]], 1);
            }
        }
    }
}

// ---------------------------------------------------------------------------
// FUSED: csr-fill + layer-1 tf32 GEMM, roles INTERLEAVED by blockIdx parity
// so every scheduling wave co-resides both workloads on each SM.
// ---------------------------------------------------------------------------
__global__ __launch_bounds__(256)
void fill_gemm1_kernel(const int* __restrict__ ei, int E,
                       int* __restrict__ cursor, int* __restrict__ csr,
                       int fillBlocks, int gemmBlocks,
                       const float* __restrict__ in, const uint32_t* __restrict__ wf,
                       __half* __restrict__ out, int n) {
    __shared__ float hT[3][64][36];

    // Interleaved role assignment: even -> fill, odd -> gemm, remainder -> larger side.
    const int paired = 2 * min(fillBlocks, gemmBlocks);
    bool isFill;
    int bid;
    if ((int)blockIdx.x < paired) {
        isFill = !(blockIdx.x & 1);
        bid = blockIdx.x >> 1;
    } else {
        int r = blockIdx.x - paired;
        isFill = (fillBlocks > gemmBlocks);
        bid = min(fillBlocks, gemmBlocks) + r;
    }

    if (isFill) {
        // ---- fill body: 4 edges/thread via int4 ----
        int e0 = (bid * 256 + threadIdx.x) * 4;
        if (e0 + 3 < E && (E & 3) == 0) {
            int4 s4 = *(const int4*)&ei[e0];
            int4 d4 = *(const int4*)&ei[E + e0];
            csr[atomicAdd(&cursor[d4.x], 1)] = s4.x;
            csr[atomicAdd(&cursor[d4.y], 1)] = s4.y;
            csr[atomicAdd(&cursor[d4.z], 1)] = s4.z;
            csr[atomicAdd(&cursor[d4.w], 1)] = s4.w;
        } else {
            for (int j = 0; j < 4; j++) {
                int e = e0 + j;
                if (e < E) {
                    int src = ei[e];
                    int dst = ei[E + e];
                    csr[atomicAdd(&cursor[dst], 1)] = src;
                }
            }
        }
        return;
    }

    // ---- GEMM body: tf32, K=128, 64 rows/block, 3-stage cp.async ----
    constexpr int NCHUNK = 4;
    const int tid  = threadIdx.x;
    const int w    = tid >> 5;
    const int lane = tid & 31;
    const int grp  = lane >> 2;
    const int tig  = lane & 3;
    const int wg   = w >> 1;
    const int cw   = w & 1;
    const int row0 = bid * 64;

    const int lr0 = wg * 16 + grp;
    const int lr1 = lr0 + 8;
    const uint4* wf4 = (const uint4*)wf;

    float acc[4][4];
#pragma unroll
    for (int nb = 0; nb < 4; nb++)
#pragma unroll
        for (int j = 0; j < 4; j++) acc[nb][j] = 0.f;

    auto stage = [&](int c, int buf) {
#pragma unroll
        for (int it = 0; it < 2; it++) {
            int idx = tid + it * 256;
            int r = idx >> 3;
            int q = idx & 7;
            int grow = row0 + r;
            uint32_t sa = (uint32_t)__cvta_generic_to_shared(&hT[buf][r][q * 4]);
            cp_async16(sa, &in[(long)grow * 128 + c * 32 + q * 4], grow < n);
        }
        asm volatile("cp.async.commit_group;");
    };

    stage(0, 0);
    stage(1, 1);

#pragma unroll
    for (int c = 0; c < NCHUNK; c++) {
        if (c == NCHUNK - 1) asm volatile("cp.async.wait_group 0;");
        else                 asm volatile("cp.async.wait_group 1;");
        __syncthreads();
        if (c + 2 < NCHUNK) stage(c + 2, (c + 2) % 3);

        const int buf = c % 3;
#pragma unroll
        for (int ks = 0; ks < 4; ks++) {
            uint32_t a0 = f2tf32(hT[buf][lr0][ks * 8 + tig]);
            uint32_t a1 = f2tf32(hT[buf][lr1][ks * 8 + tig]);
            uint32_t a2 = f2tf32(hT[buf][lr0][ks * 8 + tig + 4]);
            uint32_t a3 = f2tf32(hT[buf][lr1][ks * 8 + tig + 4]);

            const uint4* wbase = wf4 + ((c * 4 + ks) * 4 + cw * 2) * 32 + lane;
#pragma unroll
            for (int nbp = 0; nbp < 2; nbp++) {
                uint4 bb = __ldg(wbase + nbp * 32);
                asm volatile(
                    "mma.sync.aligned.m16n8k8.row.col.f32.tf32.tf32.f32 "
                    "{%0,%1,%2,%3}, {%4,%5,%6,%7}, {%8,%9}, {%0,%1,%2,%3};"
                    : "+f"(acc[nbp*2][0]), "+f"(acc[nbp*2][1]),
                      "+f"(acc[nbp*2][2]), "+f"(acc[nbp*2][3])
                    : "r"(a0), "r"(a1), "r"(a2), "r"(a3),
                      "r"(bb.x), "r"(bb.y));
                asm volatile(
                    "mma.sync.aligned.m16n8k8.row.col.f32.tf32.tf32.f32 "
                    "{%0,%1,%2,%3}, {%4,%5,%6,%7}, {%8,%9}, {%0,%1,%2,%3};"
                    : "+f"(acc[nbp*2+1][0]), "+f"(acc[nbp*2+1][1]),
                      "+f"(acc[nbp*2+1][2]), "+f"(acc[nbp*2+1][3])
                    : "r"(a0), "r"(a1), "r"(a2), "r"(a3),
                      "r"(bb.z), "r"(bb.w));
            }
        }
    }

    const int r0 = row0 + lr0;
    const int r1 = row0 + lr1;
    const bool v0 = r0 < n;
    const bool v1 = r1 < n;
#pragma unroll
    for (int nb = 0; nb < 4; nb++) {
        int col = cw * 32 + nb * 8 + tig * 2;
        if (v0) *(__half2*)&out[(long)r0 * 64 + col] = __floats2half2_rn(acc[nb][0], acc[nb][1]);
        if (v1) *(__half2*)&out[(long)r1 * 64 + col] = __floats2half2_rn(acc[nb][2], acc[nb][3]);
    }
}

// ---------------------------------------------------------------------------
// Layers 2-3 GEMM: fp16 m16n8k16, half input (K=64, single stage).
// ---------------------------------------------------------------------------
template <bool HALF_OUT>
__global__ __launch_bounds__(256)
void gemm_fp16_kernel(const __half* __restrict__ in, const uint32_t* __restrict__ wf,
                      void* __restrict__ out_, int n) {
    __shared__ __half hs[64][72];

    const int tid  = threadIdx.x;
    const int w    = tid >> 5;
    const int lane = tid & 31;
    const int grp  = lane >> 2;
    const int tig  = lane & 3;
    const int wg   = w >> 1;
    const int cw   = w & 1;
    const int row0 = blockIdx.x * 64;

    const int lr0 = wg * 16 + grp;
    const int lr1 = lr0 + 8;
    const uint4* wf4 = (const uint4*)wf;

#pragma unroll
    for (int it = 0; it < 2; it++) {
        int idx = tid + it * 256;
        int r = idx >> 3;
        int q = idx & 7;
        int grow = row0 + r;
        uint32_t sa = (uint32_t)__cvta_generic_to_shared(&hs[r][q * 8]);
        cp_async16(sa, &in[(long)grow * 64 + q * 8], grow < n);
    }
    asm volatile("cp.async.commit_group;");

    float acc[4][4];
#pragma unroll
    for (int nb = 0; nb < 4; nb++)
#pragma unroll
        for (int j = 0; j < 4; j++) acc[nb][j] = 0.f;

    asm volatile("cp.async.wait_group 0;");
    __syncthreads();

#pragma unroll
    for (int ks = 0; ks < 4; ks++) {
        uint32_t a0 = *(const uint32_t*)&hs[lr0][ks * 16 + tig * 2];
        uint32_t a1 = *(const uint32_t*)&hs[lr1][ks * 16 + tig * 2];
        uint32_t a2 = *(const uint32_t*)&hs[lr0][ks * 16 + 8 + tig * 2];
        uint32_t a3 = *(const uint32_t*)&hs[lr1][ks * 16 + 8 + tig * 2];

        const uint4* wbase = wf4 + (ks * 4 + cw * 2) * 32 + lane;
#pragma unroll
        for (int nbp = 0; nbp < 2; nbp++) {
            uint4 bb = __ldg(wbase + nbp * 32);
            asm volatile(
                "mma.sync.aligned.m16n8k16.row.col.f32.f16.f16.f32 "
                "{%0,%1,%2,%3}, {%4,%5,%6,%7}, {%8,%9}, {%0,%1,%2,%3};"
                : "+f"(acc[nbp*2][0]), "+f"(acc[nbp*2][1]),
                  "+f"(acc[nbp*2][2]), "+f"(acc[nbp*2][3])
                : "r"(a0), "r"(a1), "r"(a2), "r"(a3),
                  "r"(bb.x), "r"(bb.y));
            asm volatile(
                "mma.sync.aligned.m16n8k16.row.col.f32.f16.f16.f32 "
                "{%0,%1,%2,%3}, {%4,%5,%6,%7}, {%8,%9}, {%0,%1,%2,%3};"
                : "+f"(acc[nbp*2+1][0]), "+f"(acc[nbp*2+1][1]),
                  "+f"(acc[nbp*2+1][2]), "+f"(acc[nbp*2+1][3])
                : "r"(a0), "r"(a1), "r"(a2), "r"(a3),
                  "r"(bb.z), "r"(bb.w));
        }
    }

    const int r0 = row0 + lr0;
    const int r1 = row0 + lr1;
    const bool v0 = r0 < n;
    const bool v1 = r1 < n;
#pragma unroll
    for (int nb = 0; nb < 4; nb++) {
        int col = cw * 32 + nb * 8 + tig * 2;
        if (HALF_OUT) {
            __half* out = (__half*)out_;
            if (v0) *(__half2*)&out[(long)r0 * 64 + col] = __floats2half2_rn(acc[nb][0], acc[nb][1]);
            if (v1) *(__half2*)&out[(long)r1 * 64 + col] = __floats2half2_rn(acc[nb][2], acc[nb][3]);
        } else {
            float* out = (float*)out_;
            if (v0) *(float2*)&out[(long)r0 * 64 + col] = make_float2(acc[nb][0], acc[nb][1]);
            if (v1) *(float2*)&out[(long)r1 * 64 + col] = make_float2(acc[nb][2], acc[nb][3]);
        }
    }
}

// ---------------------------------------------------------------------------
// CSR scans
// ---------------------------------------------------------------------------
__global__ __launch_bounds__(256)
void scan1_kernel(const int* __restrict__ deg, int n,
                  int* __restrict__ incl, int* __restrict__ bsum) {
    __shared__ int s[1024];
    const int base = blockIdx.x * 1024;
    const int t = threadIdx.x;
#pragma unroll
    for (int j = 0; j < 4; j++) {
        int idx = t + j * 256;
        s[idx] = (base + idx < n) ? deg[base + idx] : 0;
    }
    __syncthreads();
    for (int off = 1; off < 1024; off <<= 1) {
        int v[4];
#pragma unroll
        for (int j = 0; j < 4; j++) {
            int idx = t + j * 256;
            v[j] = (idx >= off) ? s[idx - off] : 0;
        }
        __syncthreads();
#pragma unroll
        for (int j = 0; j < 4; j++) s[t + j * 256] += v[j];
        __syncthreads();
    }
#pragma unroll
    for (int j = 0; j < 4; j++) {
        int idx = t + j * 256;
        if (base + idx < n) incl[base + idx] = s[idx];
    }
    if (t == 0) bsum[blockIdx.x] = s[1023];
}

__global__ __launch_bounds__(256)
void scan3_kernel(const int* __restrict__ incl, int* __restrict__ deg,
                  const int* __restrict__ bsum, int nb, int n, int E,
                  int* __restrict__ rp, int* __restrict__ cursor) {
    __shared__ int s[128];
    const int t = threadIdx.x;
    if (t < 128) s[t] = (t < nb) ? bsum[t] : 0;
    __syncthreads();
    for (int off = 1; off < 128; off <<= 1) {
        int v = 0;
        if (t < 128 && t >= off) v = s[t - off];
        __syncthreads();
        if (t < 128) s[t] += v;
        __syncthreads();
    }
    int i = blockIdx.x * blockDim.x + t;
    if (i >= n) return;
    int b = i >> 10;
    int add = b ? s[b - 1] : 0;
    int excl = incl[i] - deg[i] + add;
    rp[i] = excl;
    cursor[i] = excl;
    deg[i] = 0;
    if (i == n - 1) rp[n] = E;
}

// ---------------------------------------------------------------------------
// Gather-reduce (fp16 t) + bias + relu -> fp16 h
// ---------------------------------------------------------------------------
__global__ __launch_bounds__(256)
void gather_h2_kernel(const int* __restrict__ rp, const int* __restrict__ csr,
                      const __half* __restrict__ t, const float* __restrict__ bias,
                      __half* __restrict__ out, int n) {
    int warp = (blockIdx.x * blockDim.x + threadIdx.x) >> 5;
    int lane = threadIdx.x & 31;
    if (warp >= n) return;

    int s0 = rp[warp];
    int s1 = rp[warp + 1];
    const __half2* tp = (const __half2*)t;

    float ax = 0.f, ay = 0.f, bx = 0.f, by = 0.f;
    int e = s0;
    for (; e + 15 < s1; e += 16) {
        int idx[16];
#pragma unroll
        for (int j = 0; j < 16; j++) idx[j] = __ldg(&csr[e + j]);
        float2 v[16];
#pragma unroll
        for (int j = 0; j < 16; j++)
            v[j] = __half22float2(tp[(long)idx[j] * 32 + lane]);
#pragma unroll
        for (int j = 0; j < 16; j += 4) {
            ax += v[j + 0].x + v[j + 2].x;  ay += v[j + 0].y + v[j + 2].y;
            bx += v[j + 1].x + v[j + 3].x;  by += v[j + 1].y + v[j + 3].y;
        }
    }
    for (; e + 3 < s1; e += 4) {
        int i0 = __ldg(&csr[e + 0]);
        int i1 = __ldg(&csr[e + 1]);
        int i2 = __ldg(&csr[e + 2]);
        int i3 = __ldg(&csr[e + 3]);
        float2 v0 = __half22float2(tp[(long)i0 * 32 + lane]);
        float2 v1 = __half22float2(tp[(long)i1 * 32 + lane]);
        float2 v2 = __half22float2(tp[(long)i2 * 32 + lane]);
        float2 v3 = __half22float2(tp[(long)i3 * 32 + lane]);
        ax += v0.x + v2.x;  ay += v0.y + v2.y;
        bx += v1.x + v3.x;  by += v1.y + v3.y;
    }
    for (; e < s1; e++) {
        int i0 = __ldg(&csr[e]);
        float2 v = __half22float2(tp[(long)i0 * 32 + lane]);
        ax += v.x; ay += v.y;
    }
    ax += bx; ay += by;

    float2 bb = *(const float2*)&bias[lane * 2];
    float rx = fmaxf(ax + bb.x, 0.f);
    float ry = fmaxf(ay + bb.y, 0.f);
    ((__half2*)out)[(long)warp * 32 + lane] = __floats2half2_rn(rx, ry);
}

// ---------------------------------------------------------------------------
// Final gather (fp32 t) + bias + sigmoid
// ---------------------------------------------------------------------------
__global__ __launch_bounds__(256)
void gather_f32_sig_kernel(const int* __restrict__ rp, const int* __restrict__ csr,
                           const float* __restrict__ t, const float* __restrict__ bias,
                           float* __restrict__ out, int n) {
    int warp = (blockIdx.x * blockDim.x + threadIdx.x) >> 5;
    int lane = threadIdx.x & 31;
    if (warp >= n) return;

    int s0 = rp[warp];
    int s1 = rp[warp + 1];

    float ax = 0.f, ay = 0.f, bx = 0.f, by = 0.f;
    int e = s0;
    for (; e + 7 < s1; e += 8) {
        int idx[8];
#pragma unroll
        for (int j = 0; j < 8; j++) idx[j] = __ldg(&csr[e + j]);
        float2 v[8];
#pragma unroll
        for (int j = 0; j < 8; j++)
            v[j] = *(const float2*)&t[(long)idx[j] * 64 + lane * 2];
#pragma unroll
        for (int j = 0; j < 8; j += 4) {
            ax += v[j + 0].x + v[j + 2].x;  ay += v[j + 0].y + v[j + 2].y;
            bx += v[j + 1].x + v[j + 3].x;  by += v[j + 1].y + v[j + 3].y;
        }
    }
    for (; e < s1; e++) {
        int i0 = __ldg(&csr[e]);
        float2 v = *(const float2*)&t[(long)i0 * 64 + lane * 2];
        ax += v.x; ay += v.y;
    }
    ax += bx; ay += by;

    float2 bb = *(const float2*)&bias[lane * 2];
    ax += bb.x; ay += bb.y;
    float2 r;
    r.x = 1.f / (1.f + __expf(-ax));
    r.y = 1.f / (1.f + __expf(-ay));
    *(float2*)&out[(long)warp * 64 + lane * 2] = r;
}

extern "C" void kernel_launch(void* const* d_in, const int* in_sizes, int n_in,
                              void* d_out, int out_size) {
    const float* x  = (const float*)d_in[0];
    const int*   ei = (const int*)d_in[1];
    const float* W1 = (const float*)d_in[2];
    const float* b1 = (const float*)d_in[3];
    const float* W2 = (const float*)d_in[4];
    const float* b2 = (const float*)d_in[5];
    const float* W3 = (const float*)d_in[6];
    const float* b3 = (const float*)d_in[7];
    float* out = (float*)d_out;

    const int N = in_sizes[0] / 128;
    const int E = in_sizes[1] / 2;

    __half *t16a, *t16b;
    float *t32, *hbuf;
    int *deg, *incl, *rp, *cursor, *bsum, *csr;
    uint32_t* wf;
    cudaGetSymbolAddress((void**)&t16a,   g_t16a);
    cudaGetSymbolAddress((void**)&t16b,   g_t16b);
    cudaGetSymbolAddress((void**)&t32,    g_t32);
    cudaGetSymbolAddress((void**)&hbuf,   g_h);
    cudaGetSymbolAddress((void**)&deg,    g_deg);
    cudaGetSymbolAddress((void**)&incl,   g_incl);
    cudaGetSymbolAddress((void**)&rp,     g_rp);
    cudaGetSymbolAddress((void**)&cursor, g_cursor);
    cudaGetSymbolAddress((void**)&bsum,   g_bsum);
    cudaGetSymbolAddress((void**)&csr,    g_csr);
    cudaGetSymbolAddress((void**)&wf,     g_wf);

    __half* h16a = (__half*)hbuf;
    __half* h16b = (__half*)hbuf + (long)NMAX * 64;

    const int nb_scan = (N + 1023) / 1024;
    const int nblk  = (N + 255) / 256;
    const int eblk4 = (E + 1023) / 1024;   // fill blocks (4 edges/thread)
    const int gb64  = (N + 63) / 64;       // gemm blocks
    const int wb    = (N + 7) / 8;

    hist_wprep_kernel<<<eblk4 + 3, 256>>>(ei, E, deg, W1, W2, W3, wf);       // 1
    scan1_kernel<<<nb_scan, 256>>>(deg, N, incl, bsum);                      // 2
    scan3_kernel<<<nblk, 256>>>(incl, deg, bsum, nb_scan, N, E, rp, cursor); // 3
    // 4 (profiled): fill + gemm1 fused, roles interleaved for true overlap
    fill_gemm1_kernel<<<eblk4 + gb64, 256>>>(ei, E, cursor, csr, eblk4, gb64,
                                             x, wf, t16a, N);

    gather_h2_kernel<<<wb, 256>>>(rp, csr, t16a, b1, h16a, N);               // 5
    gemm_fp16_kernel<true><<<gb64, 256>>>(h16a, wf + 8192, t16b, N);         // 6
    gather_h2_kernel<<<wb, 256>>>(rp, csr, t16b, b2, h16b, N);               // 7
    gemm_fp16_kernel<false><<<gb64, 256>>>(h16b, wf + 10240, t32, N);        // 8
    gather_f32_sig_kernel<<<wb, 256>>>(rp, csr, t32, b3, out, N);            // 9
}